// round 3
// baseline (speedup 1.0000x reference)
#include <cuda_runtime.h>

// out[m,o] = sum_c |x[m,c] - w[c,o]| + b[o]
//          = 2*sum_c max(x[m,c], w[c,o]) - Sx[m] - Sw[o] + b[o]
// Hot loop: FMNMX (alu pipe) + FADD (fma pipe), dual-pipe balanced.
// Small tiles (32x64) + 1568 blocks -> HW block scheduler load-balances,
// killing the wave-quantization tail seen at 784 blocks.

constexpr int C    = 64;    // channels (reduction dim)
constexpr int OUTC = 128;   // output channels
constexpr int BM   = 32;    // rows per block
constexpr int BO   = 64;    // output cols per block
constexpr int XS   = 36;    // padded stride for transposed x tile (32 + 4)

__global__ __launch_bounds__(128)
void lp1_maxtrick_kernel(const float* __restrict__ x,
                         const float* __restrict__ w,
                         const float* __restrict__ b,
                         float* __restrict__ out)
{
    __shared__ float w_s[C * BO];   // [c][o]  16 KB
    __shared__ float x_s[C * XS];   // [c][m]  9.2 KB (transposed, padded)
    __shared__ float sx_s[BM];
    __shared__ float beta_s[BO];

    const int tid   = threadIdx.x;
    const int m_blk = blockIdx.x * BM;
    const int o_blk = blockIdx.y * BO;

    // ---- stage w slice [C][BO]: 1024 float4, 8 per thread ----
    #pragma unroll
    for (int i = 0; i < 8; ++i) {
        int idx = tid + 128 * i;
        int c   = idx >> 4;                 // 16 float4 per c-row
        int o4  = idx & 15;
        float4 v = *(const float4*)(w + c * OUTC + o_blk + o4 * 4);
        *(float4*)(&w_s[c * BO + o4 * 4]) = v;
    }

    // ---- stage x tile transposed: 512 float4, 4 per thread ----
    #pragma unroll
    for (int i = 0; i < 4; ++i) {
        int idx = tid + 128 * i;
        int m   = idx >> 4;                 // 16 float4 per row (C=64)
        int c   = (idx & 15) << 2;
        float4 v = *(const float4*)(x + (size_t)(m_blk + m) * C + c);
        x_s[(c + 0) * XS + m] = v.x;
        x_s[(c + 1) * XS + m] = v.y;
        x_s[(c + 2) * XS + m] = v.z;
        x_s[(c + 3) * XS + m] = v.w;
    }
    __syncthreads();

    // ---- prologue: beta[o] = b[o] - Sw[o]; sx[m] = sum_c x ----
    if (tid < BO) {
        float s = 0.f;
        #pragma unroll
        for (int c = 0; c < C; ++c) s += w_s[c * BO + tid];
        beta_s[tid] = b[o_blk + tid] - s;
    } else if (tid < BO + BM) {
        int m = tid - BO;
        float s = 0.f;
        #pragma unroll
        for (int c = 0; c < C; ++c) s += x_s[c * XS + m];
        sx_s[m] = s;
    }
    __syncthreads();

    // ---- main loop: 4x4 register tile ----
    const int o0 = (tid & 15) * 4;   // 16 o-groups covering 64
    const int m0 = (tid >> 4) * 4;   // 8 m-groups covering 32

    float acc[4][4];
    #pragma unroll
    for (int i = 0; i < 4; ++i)
        #pragma unroll
        for (int j = 0; j < 4; ++j) acc[i][j] = 0.f;

    float4 xv = *(const float4*)(&x_s[m0]);
    float4 wv = *(const float4*)(&w_s[o0]);

    #pragma unroll
    for (int c = 0; c < C; ++c) {
        float4 xn, wn;
        if (c + 1 < C) {                 // compile-time guard (full unroll)
            xn = *(const float4*)(&x_s[(c + 1) * XS + m0]);
            wn = *(const float4*)(&w_s[(c + 1) * BO + o0]);
        }
        float xa[4] = {xv.x, xv.y, xv.z, xv.w};
        float wa[4] = {wv.x, wv.y, wv.z, wv.w};
        #pragma unroll
        for (int i = 0; i < 4; ++i)
            #pragma unroll
            for (int j = 0; j < 4; ++j)
                acc[i][j] += fmaxf(xa[i], wa[j]);   // FMNMX (alu) + FADD (fma)
        if (c + 1 < C) { xv = xn; wv = wn; }
    }

    // ---- epilogue: out = 2*acc - sx + beta ----
    float bet[4];
    #pragma unroll
    for (int j = 0; j < 4; ++j) bet[j] = beta_s[o0 + j];

    #pragma unroll
    for (int i = 0; i < 4; ++i) {
        float base = -sx_s[m0 + i];
        float4 r;
        r.x = fmaf(2.f, acc[i][0], base + bet[0]);
        r.y = fmaf(2.f, acc[i][1], base + bet[1]);
        r.z = fmaf(2.f, acc[i][2], base + bet[2]);
        r.w = fmaf(2.f, acc[i][3], base + bet[3]);
        *(float4*)(out + (size_t)(m_blk + m0 + i) * OUTC + o_blk + o0) = r;
    }
}

extern "C" void kernel_launch(void* const* d_in, const int* in_sizes, int n_in,
                              void* d_out, int out_size)
{
    const float* x = (const float*)d_in[0];   // [M, 64]
    const float* w = (const float*)d_in[1];   // [64, 128]
    const float* b = (const float*)d_in[2];   // [128]
    float* out = (float*)d_out;               // [M, 128]

    int M = in_sizes[0] / C;                  // 25088
    dim3 grid(M / BM, OUTC / BO);             // (784, 2) = 1568 blocks
    lp1_maxtrick_kernel<<<grid, 128>>>(x, w, b, out);
}

// round 4
// speedup vs baseline: 1.4100x; 1.4100x over previous
#include <cuda_runtime.h>

// out[m,o] = sum_c |x[m,c] - w[c,o]| + b[o]
//          = 2*sum_c max(x[m,c], w[c,o]) - Sx[m] - Sw[o] + b[o]
// 4(m) x 8(o) register tile: 3 LDS.128 feed 32 MACs (2x fewer LDS/MAC than R1).

constexpr int C    = 64;    // channels (reduction dim)
constexpr int OUTC = 128;   // output channels
constexpr int BM   = 64;    // rows per block
constexpr int BO   = 128;   // output cols per block (= OUTC, whole w staged)
constexpr int XS   = 68;    // padded stride for transposed x tile

__global__ __launch_bounds__(256, 4)
void lp1_maxtrick_kernel(const float* __restrict__ x,
                         const float* __restrict__ w,
                         const float* __restrict__ b,
                         float* __restrict__ out)
{
    __shared__ float w_s[C * BO];   // [c][o]  32 KB
    __shared__ float x_s[C * XS];   // [c][m]  17.4 KB (transposed, padded)
    __shared__ float sx_s[BM];
    __shared__ float beta_s[BO];

    const int tid   = threadIdx.x;
    const int m_blk = blockIdx.x * BM;

    // ---- stage whole w [C][128]: 2048 float4, 8 per thread (coalesced) ----
    #pragma unroll
    for (int i = 0; i < 8; ++i) {
        int idx = tid + 256 * i;            // 0..2047
        *(float4*)(&w_s[idx * 4]) = *(const float4*)(w + idx * 4);
    }

    // ---- stage x tile transposed: 1024 float4, 4 per thread ----
    #pragma unroll
    for (int i = 0; i < 4; ++i) {
        int idx = tid + 256 * i;
        int m   = idx >> 4;                 // 16 float4 per row (C=64)
        int c   = (idx & 15) << 2;
        float4 v = *(const float4*)(x + (size_t)(m_blk + m) * C + c);
        x_s[(c + 0) * XS + m] = v.x;
        x_s[(c + 1) * XS + m] = v.y;
        x_s[(c + 2) * XS + m] = v.z;
        x_s[(c + 3) * XS + m] = v.w;
    }
    __syncthreads();

    // ---- prologue: beta[o] = b[o] - Sw[o]; sx[m] = sum_c x ----
    if (tid < BO) {
        float s = 0.f;
        #pragma unroll
        for (int c = 0; c < C; ++c) s += w_s[c * BO + tid];
        beta_s[tid] = b[tid] - s;
    } else if (tid < BO + BM) {
        int m = tid - BO;
        float s = 0.f;
        #pragma unroll
        for (int c = 0; c < C; ++c) s += x_s[c * XS + m];
        sx_s[m] = s;
    }
    __syncthreads();

    // ---- main loop: 4(m) x 8(o) register tile ----
    const int o0 = (tid & 15) * 8;   // 16 o-groups covering 128
    const int m0 = (tid >> 4) * 4;   // 16 m-groups covering 64

    float acc[4][8];
    #pragma unroll
    for (int i = 0; i < 4; ++i)
        #pragma unroll
        for (int j = 0; j < 8; ++j) acc[i][j] = 0.f;

    #pragma unroll 16
    for (int c = 0; c < C; ++c) {
        float4 xv  = *(const float4*)(&x_s[c * XS + m0]);
        float4 wv0 = *(const float4*)(&w_s[c * BO + o0]);
        float4 wv1 = *(const float4*)(&w_s[c * BO + o0 + 4]);
        float xa[4] = {xv.x, xv.y, xv.z, xv.w};
        float wa[8] = {wv0.x, wv0.y, wv0.z, wv0.w,
                       wv1.x, wv1.y, wv1.z, wv1.w};
        #pragma unroll
        for (int i = 0; i < 4; ++i)
            #pragma unroll
            for (int j = 0; j < 8; ++j)
                acc[i][j] += fmaxf(xa[i], wa[j]);   // FMNMX (alu) + FADD (fma)
    }

    // ---- epilogue: out = 2*acc - sx + beta ----
    float bet[8];
    #pragma unroll
    for (int j = 0; j < 8; ++j) bet[j] = beta_s[o0 + j];

    #pragma unroll
    for (int i = 0; i < 4; ++i) {
        float base = -sx_s[m0 + i];
        float* op = out + (size_t)(m_blk + m0 + i) * OUTC + o0;
        float4 r0, r1;
        r0.x = fmaf(2.f, acc[i][0], base + bet[0]);
        r0.y = fmaf(2.f, acc[i][1], base + bet[1]);
        r0.z = fmaf(2.f, acc[i][2], base + bet[2]);
        r0.w = fmaf(2.f, acc[i][3], base + bet[3]);
        r1.x = fmaf(2.f, acc[i][4], base + bet[4]);
        r1.y = fmaf(2.f, acc[i][5], base + bet[5]);
        r1.z = fmaf(2.f, acc[i][6], base + bet[6]);
        r1.w = fmaf(2.f, acc[i][7], base + bet[7]);
        *(float4*)(op)     = r0;
        *(float4*)(op + 4) = r1;
    }
}

extern "C" void kernel_launch(void* const* d_in, const int* in_sizes, int n_in,
                              void* d_out, int out_size)
{
    const float* x = (const float*)d_in[0];   // [M, 64]
    const float* w = (const float*)d_in[1];   // [64, 128]
    const float* b = (const float*)d_in[2];   // [128]
    float* out = (float*)d_out;               // [M, 128]

    int M = in_sizes[0] / C;                  // 25088
    dim3 grid(M / BM, 1);                     // (392, 1)
    lp1_maxtrick_kernel<<<grid, 256>>>(x, w, b, out);
}